// round 1
// baseline (speedup 1.0000x reference)
#include <cuda_runtime.h>
#include <math.h>

// dims
#define NTOK   4096      // B*S
#define DMODEL 2048
#define MWIDTH 5632
#define NEXP   8
#define RANK   16
#define ERANK  128       // NEXP*RANK
#define FSCALE 2.0f      // LORA_ALPHA / R

// scratch (alloc-free rule: __device__ globals)
__device__ float g_h [(size_t)NTOK * MWIDTH];   // SwiGLU hidden
__device__ float g_cg[NTOK * ERANK];            // routing-weighted LoRA coeffs (gate)
__device__ float g_cu[NTOK * ERANK];            // (up)
__device__ float g_cd[NTOK * ERANK];            // (down)

// ---------------------------------------------------------------------------
// K1: router logits -> softmax/argmax -> routing & expert_choice outputs,
//     plus h_g = x@Ag^T, h_u = x@Au^T folded into c_g, c_u coefficients.
// One block per token, 256 threads (8 warps x 5 dot products each = 40 dots).
// ---------------------------------------------------------------------------
__global__ void k_router(const float* __restrict__ x,  const float* __restrict__ Wr,
                         const float* __restrict__ br, const float* __restrict__ Ag,
                         const float* __restrict__ Au,
                         float* __restrict__ out_routing, float* __restrict__ out_choice)
{
    __shared__ float xs[DMODEL];
    __shared__ float red[40];            // [0..7]=logits dot, [8..23]=h_g, [24..39]=h_u
    __shared__ float routing_s[NEXP];
    __shared__ int   amax_s;

    const int t = blockIdx.x;
    const float* xrow = x + (size_t)t * DMODEL;
    for (int i = threadIdx.x; i < DMODEL / 4; i += blockDim.x)
        ((float4*)xs)[i] = ((const float4*)xrow)[i];
    __syncthreads();

    const int w = threadIdx.x >> 5, lane = threadIdx.x & 31;
    #pragma unroll
    for (int q = 0; q < 5; ++q) {
        const int o = w + 8 * q;
        const float* wrow = (o < 8)  ? (Wr + o * DMODEL)
                          : (o < 24) ? (Ag + (o - 8) * DMODEL)
                                     : (Au + (o - 24) * DMODEL);
        float s = 0.f;
        for (int k = lane; k < DMODEL; k += 32) s = fmaf(xs[k], wrow[k], s);
        #pragma unroll
        for (int off = 16; off; off >>= 1) s += __shfl_xor_sync(0xffffffffu, s, off);
        if (lane == 0) red[o] = s;
    }
    __syncthreads();

    if (threadIdx.x == 0) {
        float lg[NEXP]; float mx = -1e30f;
        #pragma unroll
        for (int e = 0; e < NEXP; ++e) { lg[e] = red[e] + br[e]; mx = fmaxf(mx, lg[e]); }
        float sum = 0.f;
        #pragma unroll
        for (int e = 0; e < NEXP; ++e) { lg[e] = expf(lg[e] - mx); sum += lg[e]; }
        const float inv = 1.f / sum;
        int am = 0; float best = -1.f;
        #pragma unroll
        for (int e = 0; e < NEXP; ++e) {
            const float r = lg[e] * inv; routing_s[e] = r;
            if (r > best) { best = r; am = e; }   // strict > : first-max like jnp.argmax
        }
        amax_s = am;
    }
    __syncthreads();

    if (threadIdx.x < NEXP) {
        const float r  = routing_s[threadIdx.x];
        out_routing[t * NEXP + threadIdx.x] = r;
        const float yh = (threadIdx.x == amax_s) ? 1.f : 0.f;
        out_choice[t * NEXP + threadIdx.x] = (yh - r) + r;   // straight-through forward
    }
    const int j = threadIdx.x & 127;
    const int e = j >> 4, rr = j & 15;
    if (threadIdx.x < 128) g_cg[t * ERANK + j] = routing_s[e] * red[8  + rr] * FSCALE;
    else                   g_cu[t * ERANK + j] = routing_s[e] * red[24 + rr] * FSCALE;
}

// ---------------------------------------------------------------------------
// K3: h_d = h@Ad^T  ->  c_d = routing * h_d * scale.  One block per token.
// ---------------------------------------------------------------------------
__global__ void k_hd(const float* __restrict__ Ad, const float* __restrict__ routing)
{
    __shared__ float hs[MWIDTH];
    __shared__ float red[RANK];
    const int t = blockIdx.x;
    const float* hrow = g_h + (size_t)t * MWIDTH;
    for (int i = threadIdx.x; i < MWIDTH / 4; i += blockDim.x)
        ((float4*)hs)[i] = ((const float4*)hrow)[i];
    __syncthreads();

    const int w = threadIdx.x >> 5, lane = threadIdx.x & 31;
    #pragma unroll
    for (int q = 0; q < 2; ++q) {
        const int r = w * 2 + q;
        const float* arow = Ad + r * MWIDTH;
        float s = 0.f;
        for (int k = lane; k < MWIDTH; k += 32) s = fmaf(hs[k], arow[k], s);
        #pragma unroll
        for (int off = 16; off; off >>= 1) s += __shfl_xor_sync(0xffffffffu, s, off);
        if (lane == 0) red[r] = s;
    }
    __syncthreads();
    if (threadIdx.x < 128) {
        const int e = threadIdx.x >> 4, rr = threadIdx.x & 15;
        g_cd[t * ERANK + threadIdx.x] = routing[t * NEXP + e] * red[rr] * FSCALE;
    }
}

// ---------------------------------------------------------------------------
// K2/K4: NT GEMM  C = A @ B^T  (+ rank-128 LoRA augmentation as 8 extra K-tiles)
//   DUAL=true : A=x, B0=Wg, B1=Wu, aug A's = c_g/c_u, aug B's = Bg/Bu.
//               Epilogue h = silu(gate)*up -> g_h.
//   DUAL=false: A=g_h, B0=Wd, aug = c_d/Bd. Epilogue -> d_out.
// BM=128, BK=16, BN = 64 (dual) / 128 (single), 256 thr, thread tile 8x4 / 8x8.
// ---------------------------------------------------------------------------
template<bool DUAL>
__global__ __launch_bounds__(256, 2)
void k_gemm(const float* __restrict__ Ain, int K,
            const float* __restrict__ B0,  const float* __restrict__ B1,
            const float* __restrict__ BE0, const float* __restrict__ BE1,
            int Ntot, float* __restrict__ OutP)
{
    constexpr int BM = 128, BK = 16;
    constexpr int BN = DUAL ? 64 : 128;
    constexpr int TM = 8,  TN = BN / 16;
    constexpr int NITB = (BN * BK / 4) / 256;   // B-tile float4 loads per thread

    __shared__ float As [BK * BM];
    __shared__ float As2[DUAL ? BK * BM : 1];
    __shared__ float Bs0[BK * BN];
    __shared__ float Bs1[DUAL ? BK * BN : 1];

    const float* A   = DUAL ? Ain  : g_h;
    const float* CA0 = DUAL ? g_cg : g_cd;
    float*       Out = DUAL ? g_h  : OutP;

    const int m0 = blockIdx.y * BM;
    const int n0 = blockIdx.x * BN;
    const int tid = threadIdx.x;
    const int tx = tid & 15, ty = tid >> 4;

    float acc0[TM][TN];
    float acc1[DUAL ? TM : 1][DUAL ? TN : 1];
    #pragma unroll
    for (int i = 0; i < TM; ++i)
        #pragma unroll
        for (int j = 0; j < TN; ++j) acc0[i][j] = 0.f;
    if constexpr (DUAL) {
        #pragma unroll
        for (int i = 0; i < TM; ++i)
            #pragma unroll
            for (int j = 0; j < TN; ++j) acc1[i][j] = 0.f;
    }

    // ---------------- main K loop (shared A operand) ----------------
    const int nkt = K / BK;
    for (int kt = 0; kt < nkt; ++kt) {
        {   // A tile: BM x BK, transposed into As[k][m]
            const float* src = A + (size_t)m0 * K + kt * BK;
            #pragma unroll
            for (int it = 0; it < 2; ++it) {
                const int v = tid + it * 256, row = v >> 2, kv = v & 3;
                float4 f = *(const float4*)(src + (size_t)row * K + kv * 4);
                As[(kv*4+0)*BM + row] = f.x;  As[(kv*4+1)*BM + row] = f.y;
                As[(kv*4+2)*BM + row] = f.z;  As[(kv*4+3)*BM + row] = f.w;
            }
        }
        {   // B tiles: BN x BK, transposed into Bs[k][n]
            const float* src = B0 + (size_t)n0 * K + kt * BK;
            #pragma unroll
            for (int it = 0; it < NITB; ++it) {
                const int v = tid + it * 256, row = v >> 2, kv = v & 3;
                float4 f = *(const float4*)(src + (size_t)row * K + kv * 4);
                Bs0[(kv*4+0)*BN + row] = f.x;  Bs0[(kv*4+1)*BN + row] = f.y;
                Bs0[(kv*4+2)*BN + row] = f.z;  Bs0[(kv*4+3)*BN + row] = f.w;
            }
            if constexpr (DUAL) {
                const float* s1 = B1 + (size_t)n0 * K + kt * BK;
                #pragma unroll
                for (int it = 0; it < NITB; ++it) {
                    const int v = tid + it * 256, row = v >> 2, kv = v & 3;
                    float4 f = *(const float4*)(s1 + (size_t)row * K + kv * 4);
                    Bs1[(kv*4+0)*BN + row] = f.x;  Bs1[(kv*4+1)*BN + row] = f.y;
                    Bs1[(kv*4+2)*BN + row] = f.z;  Bs1[(kv*4+3)*BN + row] = f.w;
                }
            }
        }
        __syncthreads();
        #pragma unroll
        for (int k = 0; k < BK; ++k) {
            float af[TM];
            *(float4*)&af[0] = *(const float4*)&As[k*BM + ty*TM];
            *(float4*)&af[4] = *(const float4*)&As[k*BM + ty*TM + 4];
            float bf0[TN];
            #pragma unroll
            for (int jv = 0; jv < TN/4; ++jv)
                *(float4*)&bf0[jv*4] = *(const float4*)&Bs0[k*BN + tx*TN + jv*4];
            if constexpr (DUAL) {
                float bf1[TN];
                #pragma unroll
                for (int jv = 0; jv < TN/4; ++jv)
                    *(float4*)&bf1[jv*4] = *(const float4*)&Bs1[k*BN + tx*TN + jv*4];
                #pragma unroll
                for (int i = 0; i < TM; ++i)
                    #pragma unroll
                    for (int j = 0; j < TN; ++j) {
                        acc0[i][j] = fmaf(af[i], bf0[j], acc0[i][j]);
                        acc1[i][j] = fmaf(af[i], bf1[j], acc1[i][j]);
                    }
            } else {
                #pragma unroll
                for (int i = 0; i < TM; ++i)
                    #pragma unroll
                    for (int j = 0; j < TN; ++j)
                        acc0[i][j] = fmaf(af[i], bf0[j], acc0[i][j]);
            }
        }
        __syncthreads();
    }

    // ---------------- LoRA augmentation: 8 extra K-tiles over rank 128 -------
    #pragma unroll 1
    for (int e = 0; e < ERANK / BK; ++e) {
        {   // coefficient tiles (per-accumulator A operands)
            const float* src = CA0 + (size_t)m0 * ERANK + e * BK;
            #pragma unroll
            for (int it = 0; it < 2; ++it) {
                const int v = tid + it * 256, row = v >> 2, kv = v & 3;
                float4 f = *(const float4*)(src + (size_t)row * ERANK + kv * 4);
                As[(kv*4+0)*BM + row] = f.x;  As[(kv*4+1)*BM + row] = f.y;
                As[(kv*4+2)*BM + row] = f.z;  As[(kv*4+3)*BM + row] = f.w;
            }
            if constexpr (DUAL) {
                const float* s2 = g_cu + (size_t)m0 * ERANK + e * BK;
                #pragma unroll
                for (int it = 0; it < 2; ++it) {
                    const int v = tid + it * 256, row = v >> 2, kv = v & 3;
                    float4 f = *(const float4*)(s2 + (size_t)row * ERANK + kv * 4);
                    As2[(kv*4+0)*BM + row] = f.x;  As2[(kv*4+1)*BM + row] = f.y;
                    As2[(kv*4+2)*BM + row] = f.z;  As2[(kv*4+3)*BM + row] = f.w;
                }
            }
        }
        {   // expert-B tiles: B[e, n, 0..15] is contiguous over r
            const float* src = BE0 + ((size_t)e * Ntot + n0) * RANK;
            #pragma unroll
            for (int it = 0; it < NITB; ++it) {
                const int v = tid + it * 256, row = v >> 2, kv = v & 3;
                float4 f = *(const float4*)(src + (size_t)row * RANK + kv * 4);
                Bs0[(kv*4+0)*BN + row] = f.x;  Bs0[(kv*4+1)*BN + row] = f.y;
                Bs0[(kv*4+2)*BN + row] = f.z;  Bs0[(kv*4+3)*BN + row] = f.w;
            }
            if constexpr (DUAL) {
                const float* s1 = BE1 + ((size_t)e * Ntot + n0) * RANK;
                #pragma unroll
                for (int it = 0; it < NITB; ++it) {
                    const int v = tid + it * 256, row = v >> 2, kv = v & 3;
                    float4 f = *(const float4*)(s1 + (size_t)row * RANK + kv * 4);
                    Bs1[(kv*4+0)*BN + row] = f.x;  Bs1[(kv*4+1)*BN + row] = f.y;
                    Bs1[(kv*4+2)*BN + row] = f.z;  Bs1[(kv*4+3)*BN + row] = f.w;
                }
            }
        }
        __syncthreads();
        #pragma unroll
        for (int k = 0; k < BK; ++k) {
            float af[TM];
            *(float4*)&af[0] = *(const float4*)&As[k*BM + ty*TM];
            *(float4*)&af[4] = *(const float4*)&As[k*BM + ty*TM + 4];
            float bf0[TN];
            #pragma unroll
            for (int jv = 0; jv < TN/4; ++jv)
                *(float4*)&bf0[jv*4] = *(const float4*)&Bs0[k*BN + tx*TN + jv*4];
            if constexpr (DUAL) {
                float af2[TM];
                *(float4*)&af2[0] = *(const float4*)&As2[k*BM + ty*TM];
                *(float4*)&af2[4] = *(const float4*)&As2[k*BM + ty*TM + 4];
                float bf1[TN];
                #pragma unroll
                for (int jv = 0; jv < TN/4; ++jv)
                    *(float4*)&bf1[jv*4] = *(const float4*)&Bs1[k*BN + tx*TN + jv*4];
                #pragma unroll
                for (int i = 0; i < TM; ++i)
                    #pragma unroll
                    for (int j = 0; j < TN; ++j) {
                        acc0[i][j] = fmaf(af[i],  bf0[j], acc0[i][j]);
                        acc1[i][j] = fmaf(af2[i], bf1[j], acc1[i][j]);
                    }
            } else {
                #pragma unroll
                for (int i = 0; i < TM; ++i)
                    #pragma unroll
                    for (int j = 0; j < TN; ++j)
                        acc0[i][j] = fmaf(af[i], bf0[j], acc0[i][j]);
            }
        }
        __syncthreads();
    }

    // ---------------- epilogue ----------------
    #pragma unroll
    for (int i = 0; i < TM; ++i) {
        const int row = m0 + ty * TM + i;
        #pragma unroll
        for (int jv = 0; jv < TN / 4; ++jv) {
            float4 o;
            float* op = &o.x;
            #pragma unroll
            for (int jj = 0; jj < 4; ++jj) {
                const int j = jv * 4 + jj;
                if constexpr (DUAL) {
                    const float g = acc0[i][j], u = acc1[i][j];
                    op[jj] = g * u / (1.f + expf(-g));     // silu(g)*u
                } else {
                    op[jj] = acc0[i][j];
                }
            }
            *(float4*)&Out[(size_t)row * Ntot + n0 + tx * TN + jv * 4] = o;
        }
    }
}

// ---------------------------------------------------------------------------
extern "C" void kernel_launch(void* const* d_in, const int* in_sizes, int n_in,
                              void* d_out, int out_size)
{
    const float* x  = (const float*)d_in[0];
    const float* Wr = (const float*)d_in[1];
    const float* br = (const float*)d_in[2];
    const float* Wg = (const float*)d_in[3];
    const float* Wu = (const float*)d_in[4];
    const float* Wd = (const float*)d_in[5];
    const float* Ag = (const float*)d_in[6];
    const float* Au = (const float*)d_in[7];
    const float* Ad = (const float*)d_in[8];
    const float* Bg = (const float*)d_in[9];
    const float* Bu = (const float*)d_in[10];
    const float* Bd = (const float*)d_in[11];

    float* out     = (float*)d_out;
    float* routing = out + (size_t)NTOK * DMODEL;
    float* choice  = routing + NTOK * NEXP;

    // K1: router + c_g/c_u
    k_router<<<NTOK, 256>>>(x, Wr, br, Ag, Au, routing, choice);
    // K2: fused gate/up GEMM (+LoRA) -> h = silu(gate)*up
    k_gemm<true><<<dim3(MWIDTH / 64, NTOK / 128), 256>>>(
        x, DMODEL, Wg, Wu, Bg, Bu, MWIDTH, nullptr);
    // K3: h_d -> c_d
    k_hd<<<NTOK, 256>>>(Ad, routing);
    // K4: down GEMM (+LoRA) -> out
    k_gemm<false><<<dim3(DMODEL / 128, NTOK / 128), 256>>>(
        nullptr, MWIDTH, Wd, nullptr, Bd, nullptr, DMODEL, out);
}

// round 2
// speedup vs baseline: 1.0001x; 1.0001x over previous
#include <cuda_runtime.h>
#include <math.h>

// dims
#define NTOK   4096      // B*S
#define DMODEL 2048
#define MWIDTH 5632
#define NEXP   8
#define RANK   16
#define ERANK  128       // NEXP*RANK
#define FSCALE 2.0f      // LORA_ALPHA / R

// scratch (alloc-free rule: __device__ globals)
__device__ float g_h [(size_t)NTOK * MWIDTH];   // SwiGLU hidden
__device__ float g_cg[NTOK * ERANK];            // routing-weighted LoRA coeffs (gate)
__device__ float g_cu[NTOK * ERANK];            // (up)
__device__ float g_cd[NTOK * ERANK];            // (down)

// ---------------------------------------------------------------------------
// K1: router logits -> softmax/argmax -> routing & expert_choice outputs,
//     plus h_g = x@Ag^T, h_u = x@Au^T folded into c_g, c_u coefficients.
// One block per token, 256 threads (8 warps x 5 dot products each = 40 dots).
// ---------------------------------------------------------------------------
__global__ void k_router(const float* __restrict__ x,  const float* __restrict__ Wr,
                         const float* __restrict__ br, const float* __restrict__ Ag,
                         const float* __restrict__ Au,
                         float* __restrict__ out_routing, float* __restrict__ out_choice)
{
    __shared__ float xs[DMODEL];
    __shared__ float red[40];            // [0..7]=logits dot, [8..23]=h_g, [24..39]=h_u
    __shared__ float routing_s[NEXP];
    __shared__ int   amax_s;

    const int t = blockIdx.x;
    const float* xrow = x + (size_t)t * DMODEL;
    for (int i = threadIdx.x; i < DMODEL / 4; i += blockDim.x)
        ((float4*)xs)[i] = ((const float4*)xrow)[i];
    __syncthreads();

    const int w = threadIdx.x >> 5, lane = threadIdx.x & 31;
    #pragma unroll
    for (int q = 0; q < 5; ++q) {
        const int o = w + 8 * q;
        const float* wrow = (o < 8)  ? (Wr + o * DMODEL)
                          : (o < 24) ? (Ag + (o - 8) * DMODEL)
                                     : (Au + (o - 24) * DMODEL);
        float s = 0.f;
        for (int k = lane; k < DMODEL; k += 32) s = fmaf(xs[k], wrow[k], s);
        #pragma unroll
        for (int off = 16; off; off >>= 1) s += __shfl_xor_sync(0xffffffffu, s, off);
        if (lane == 0) red[o] = s;
    }
    __syncthreads();

    if (threadIdx.x == 0) {
        float lg[NEXP]; float mx = -1e30f;
        #pragma unroll
        for (int e = 0; e < NEXP; ++e) { lg[e] = red[e] + br[e]; mx = fmaxf(mx, lg[e]); }
        float sum = 0.f;
        #pragma unroll
        for (int e = 0; e < NEXP; ++e) { lg[e] = expf(lg[e] - mx); sum += lg[e]; }
        const float inv = 1.f / sum;
        int am = 0; float best = -1.f;
        #pragma unroll
        for (int e = 0; e < NEXP; ++e) {
            const float r = lg[e] * inv; routing_s[e] = r;
            if (r > best) { best = r; am = e; }   // strict > : first-max like jnp.argmax
        }
        amax_s = am;
    }
    __syncthreads();

    if (threadIdx.x < NEXP) {
        const float r  = routing_s[threadIdx.x];
        out_routing[t * NEXP + threadIdx.x] = r;
        const float yh = (threadIdx.x == amax_s) ? 1.f : 0.f;
        out_choice[t * NEXP + threadIdx.x] = (yh - r) + r;   // straight-through forward
    }
    const int j = threadIdx.x & 127;
    const int e = j >> 4, rr = j & 15;
    if (threadIdx.x < 128) g_cg[t * ERANK + j] = routing_s[e] * red[8  + rr] * FSCALE;
    else                   g_cu[t * ERANK + j] = routing_s[e] * red[24 + rr] * FSCALE;
}

// ---------------------------------------------------------------------------
// K3: h_d = h@Ad^T  ->  c_d = routing * h_d * scale.  One block per token.
// ---------------------------------------------------------------------------
__global__ void k_hd(const float* __restrict__ Ad, const float* __restrict__ routing)
{
    __shared__ float hs[MWIDTH];
    __shared__ float red[RANK];
    const int t = blockIdx.x;
    const float* hrow = g_h + (size_t)t * MWIDTH;
    for (int i = threadIdx.x; i < MWIDTH / 4; i += blockDim.x)
        ((float4*)hs)[i] = ((const float4*)hrow)[i];
    __syncthreads();

    const int w = threadIdx.x >> 5, lane = threadIdx.x & 31;
    #pragma unroll
    for (int q = 0; q < 2; ++q) {
        const int r = w * 2 + q;
        const float* arow = Ad + r * MWIDTH;
        float s = 0.f;
        for (int k = lane; k < MWIDTH; k += 32) s = fmaf(hs[k], arow[k], s);
        #pragma unroll
        for (int off = 16; off; off >>= 1) s += __shfl_xor_sync(0xffffffffu, s, off);
        if (lane == 0) red[r] = s;
    }
    __syncthreads();
    if (threadIdx.x < 128) {
        const int e = threadIdx.x >> 4, rr = threadIdx.x & 15;
        g_cd[t * ERANK + threadIdx.x] = routing[t * NEXP + e] * red[rr] * FSCALE;
    }
}

// ---------------------------------------------------------------------------
// K2/K4: NT GEMM  C = A @ B^T  (+ rank-128 LoRA augmentation as 8 extra K-tiles)
//   DUAL=true : A=x, B0=Wg, B1=Wu, aug A's = c_g/c_u, aug B's = Bg/Bu.
//               Epilogue h = silu(gate)*up -> g_h.
//   DUAL=false: A=g_h, B0=Wd, aug = c_d/Bd. Epilogue -> d_out.
// BM=128, BK=16, BN = 64 (dual) / 128 (single), 256 thr, thread tile 8x4 / 8x8.
// ---------------------------------------------------------------------------
template<bool DUAL>
__global__ __launch_bounds__(256, 2)
void k_gemm(const float* __restrict__ Ain, int K,
            const float* __restrict__ B0,  const float* __restrict__ B1,
            const float* __restrict__ BE0, const float* __restrict__ BE1,
            int Ntot, float* __restrict__ OutP)
{
    constexpr int BM = 128, BK = 16;
    constexpr int BN = DUAL ? 64 : 128;
    constexpr int TM = 8,  TN = BN / 16;
    constexpr int NITB = (BN * BK / 4) / 256;   // B-tile float4 loads per thread

    __shared__ float As [BK * BM];
    __shared__ float As2[DUAL ? BK * BM : 1];
    __shared__ float Bs0[BK * BN];
    __shared__ float Bs1[DUAL ? BK * BN : 1];

    const float* A   = DUAL ? Ain  : g_h;
    const float* CA0 = DUAL ? g_cg : g_cd;
    float*       Out = DUAL ? g_h  : OutP;

    const int m0 = blockIdx.y * BM;
    const int n0 = blockIdx.x * BN;
    const int tid = threadIdx.x;
    const int tx = tid & 15, ty = tid >> 4;

    float acc0[TM][TN];
    float acc1[DUAL ? TM : 1][DUAL ? TN : 1];
    #pragma unroll
    for (int i = 0; i < TM; ++i)
        #pragma unroll
        for (int j = 0; j < TN; ++j) acc0[i][j] = 0.f;
    if constexpr (DUAL) {
        #pragma unroll
        for (int i = 0; i < TM; ++i)
            #pragma unroll
            for (int j = 0; j < TN; ++j) acc1[i][j] = 0.f;
    }

    // ---------------- main K loop (shared A operand) ----------------
    const int nkt = K / BK;
    for (int kt = 0; kt < nkt; ++kt) {
        {   // A tile: BM x BK, transposed into As[k][m]
            const float* src = A + (size_t)m0 * K + kt * BK;
            #pragma unroll
            for (int it = 0; it < 2; ++it) {
                const int v = tid + it * 256, row = v >> 2, kv = v & 3;
                float4 f = *(const float4*)(src + (size_t)row * K + kv * 4);
                As[(kv*4+0)*BM + row] = f.x;  As[(kv*4+1)*BM + row] = f.y;
                As[(kv*4+2)*BM + row] = f.z;  As[(kv*4+3)*BM + row] = f.w;
            }
        }
        {   // B tiles: BN x BK, transposed into Bs[k][n]
            const float* src = B0 + (size_t)n0 * K + kt * BK;
            #pragma unroll
            for (int it = 0; it < NITB; ++it) {
                const int v = tid + it * 256, row = v >> 2, kv = v & 3;
                float4 f = *(const float4*)(src + (size_t)row * K + kv * 4);
                Bs0[(kv*4+0)*BN + row] = f.x;  Bs0[(kv*4+1)*BN + row] = f.y;
                Bs0[(kv*4+2)*BN + row] = f.z;  Bs0[(kv*4+3)*BN + row] = f.w;
            }
            if constexpr (DUAL) {
                const float* s1 = B1 + (size_t)n0 * K + kt * BK;
                #pragma unroll
                for (int it = 0; it < NITB; ++it) {
                    const int v = tid + it * 256, row = v >> 2, kv = v & 3;
                    float4 f = *(const float4*)(s1 + (size_t)row * K + kv * 4);
                    Bs1[(kv*4+0)*BN + row] = f.x;  Bs1[(kv*4+1)*BN + row] = f.y;
                    Bs1[(kv*4+2)*BN + row] = f.z;  Bs1[(kv*4+3)*BN + row] = f.w;
                }
            }
        }
        __syncthreads();
        #pragma unroll
        for (int k = 0; k < BK; ++k) {
            float af[TM];
            *(float4*)&af[0] = *(const float4*)&As[k*BM + ty*TM];
            *(float4*)&af[4] = *(const float4*)&As[k*BM + ty*TM + 4];
            float bf0[TN];
            #pragma unroll
            for (int jv = 0; jv < TN/4; ++jv)
                *(float4*)&bf0[jv*4] = *(const float4*)&Bs0[k*BN + tx*TN + jv*4];
            if constexpr (DUAL) {
                float bf1[TN];
                #pragma unroll
                for (int jv = 0; jv < TN/4; ++jv)
                    *(float4*)&bf1[jv*4] = *(const float4*)&Bs1[k*BN + tx*TN + jv*4];
                #pragma unroll
                for (int i = 0; i < TM; ++i)
                    #pragma unroll
                    for (int j = 0; j < TN; ++j) {
                        acc0[i][j] = fmaf(af[i], bf0[j], acc0[i][j]);
                        acc1[i][j] = fmaf(af[i], bf1[j], acc1[i][j]);
                    }
            } else {
                #pragma unroll
                for (int i = 0; i < TM; ++i)
                    #pragma unroll
                    for (int j = 0; j < TN; ++j)
                        acc0[i][j] = fmaf(af[i], bf0[j], acc0[i][j]);
            }
        }
        __syncthreads();
    }

    // ---------------- LoRA augmentation: 8 extra K-tiles over rank 128 -------
    #pragma unroll 1
    for (int e = 0; e < ERANK / BK; ++e) {
        {   // coefficient tiles (per-accumulator A operands)
            const float* src = CA0 + (size_t)m0 * ERANK + e * BK;
            #pragma unroll
            for (int it = 0; it < 2; ++it) {
                const int v = tid + it * 256, row = v >> 2, kv = v & 3;
                float4 f = *(const float4*)(src + (size_t)row * ERANK + kv * 4);
                As[(kv*4+0)*BM + row] = f.x;  As[(kv*4+1)*BM + row] = f.y;
                As[(kv*4+2)*BM + row] = f.z;  As[(kv*4+3)*BM + row] = f.w;
            }
            if constexpr (DUAL) {
                const float* s2 = g_cu + (size_t)m0 * ERANK + e * BK;
                #pragma unroll
                for (int it = 0; it < 2; ++it) {
                    const int v = tid + it * 256, row = v >> 2, kv = v & 3;
                    float4 f = *(const float4*)(s2 + (size_t)row * ERANK + kv * 4);
                    As2[(kv*4+0)*BM + row] = f.x;  As2[(kv*4+1)*BM + row] = f.y;
                    As2[(kv*4+2)*BM + row] = f.z;  As2[(kv*4+3)*BM + row] = f.w;
                }
            }
        }
        {   // expert-B tiles: B[e, n, 0..15] is contiguous over r
            const float* src = BE0 + ((size_t)e * Ntot + n0) * RANK;
            #pragma unroll
            for (int it = 0; it < NITB; ++it) {
                const int v = tid + it * 256, row = v >> 2, kv = v & 3;
                float4 f = *(const float4*)(src + (size_t)row * RANK + kv * 4);
                Bs0[(kv*4+0)*BN + row] = f.x;  Bs0[(kv*4+1)*BN + row] = f.y;
                Bs0[(kv*4+2)*BN + row] = f.z;  Bs0[(kv*4+3)*BN + row] = f.w;
            }
            if constexpr (DUAL) {
                const float* s1 = BE1 + ((size_t)e * Ntot + n0) * RANK;
                #pragma unroll
                for (int it = 0; it < NITB; ++it) {
                    const int v = tid + it * 256, row = v >> 2, kv = v & 3;
                    float4 f = *(const float4*)(s1 + (size_t)row * RANK + kv * 4);
                    Bs1[(kv*4+0)*BN + row] = f.x;  Bs1[(kv*4+1)*BN + row] = f.y;
                    Bs1[(kv*4+2)*BN + row] = f.z;  Bs1[(kv*4+3)*BN + row] = f.w;
                }
            }
        }
        __syncthreads();
        #pragma unroll
        for (int k = 0; k < BK; ++k) {
            float af[TM];
            *(float4*)&af[0] = *(const float4*)&As[k*BM + ty*TM];
            *(float4*)&af[4] = *(const float4*)&As[k*BM + ty*TM + 4];
            float bf0[TN];
            #pragma unroll
            for (int jv = 0; jv < TN/4; ++jv)
                *(float4*)&bf0[jv*4] = *(const float4*)&Bs0[k*BN + tx*TN + jv*4];
            if constexpr (DUAL) {
                float af2[TM];
                *(float4*)&af2[0] = *(const float4*)&As2[k*BM + ty*TM];
                *(float4*)&af2[4] = *(const float4*)&As2[k*BM + ty*TM + 4];
                float bf1[TN];
                #pragma unroll
                for (int jv = 0; jv < TN/4; ++jv)
                    *(float4*)&bf1[jv*4] = *(const float4*)&Bs1[k*BN + tx*TN + jv*4];
                #pragma unroll
                for (int i = 0; i < TM; ++i)
                    #pragma unroll
                    for (int j = 0; j < TN; ++j) {
                        acc0[i][j] = fmaf(af[i],  bf0[j], acc0[i][j]);
                        acc1[i][j] = fmaf(af2[i], bf1[j], acc1[i][j]);
                    }
            } else {
                #pragma unroll
                for (int i = 0; i < TM; ++i)
                    #pragma unroll
                    for (int j = 0; j < TN; ++j)
                        acc0[i][j] = fmaf(af[i], bf0[j], acc0[i][j]);
            }
        }
        __syncthreads();
    }

    // ---------------- epilogue ----------------
    #pragma unroll
    for (int i = 0; i < TM; ++i) {
        const int row = m0 + ty * TM + i;
        #pragma unroll
        for (int jv = 0; jv < TN / 4; ++jv) {
            float4 o;
            float* op = &o.x;
            #pragma unroll
            for (int jj = 0; jj < 4; ++jj) {
                const int j = jv * 4 + jj;
                if constexpr (DUAL) {
                    const float g = acc0[i][j], u = acc1[i][j];
                    op[jj] = g * u / (1.f + expf(-g));     // silu(g)*u
                } else {
                    op[jj] = acc0[i][j];
                }
            }
            *(float4*)&Out[(size_t)row * Ntot + n0 + tx * TN + jv * 4] = o;
        }
    }
}

// ---------------------------------------------------------------------------
extern "C" void kernel_launch(void* const* d_in, const int* in_sizes, int n_in,
                              void* d_out, int out_size)
{
    const float* x  = (const float*)d_in[0];
    const float* Wr = (const float*)d_in[1];
    const float* br = (const float*)d_in[2];
    const float* Wg = (const float*)d_in[3];
    const float* Wu = (const float*)d_in[4];
    const float* Wd = (const float*)d_in[5];
    const float* Ag = (const float*)d_in[6];
    const float* Au = (const float*)d_in[7];
    const float* Ad = (const float*)d_in[8];
    const float* Bg = (const float*)d_in[9];
    const float* Bu = (const float*)d_in[10];
    const float* Bd = (const float*)d_in[11];

    float* out     = (float*)d_out;
    float* routing = out + (size_t)NTOK * DMODEL;
    float* choice  = routing + NTOK * NEXP;

    // K1: router + c_g/c_u
    k_router<<<NTOK, 256>>>(x, Wr, br, Ag, Au, routing, choice);
    // K2: fused gate/up GEMM (+LoRA) -> h = silu(gate)*up
    k_gemm<true><<<dim3(MWIDTH / 64, NTOK / 128), 256>>>(
        x, DMODEL, Wg, Wu, Bg, Bu, MWIDTH, nullptr);
    // K3: h_d -> c_d
    k_hd<<<NTOK, 256>>>(Ad, routing);
    // K4: down GEMM (+LoRA) -> out
    k_gemm<false><<<dim3(DMODEL / 128, NTOK / 128), 256>>>(
        nullptr, MWIDTH, Wd, nullptr, Bd, nullptr, DMODEL, out);
}

// round 4
// speedup vs baseline: 3.4655x; 3.4650x over previous
#include <cuda_runtime.h>
#include <cuda_fp16.h>
#include <math.h>
#include <stdint.h>

#define NTOK   4096
#define DMODEL 2048
#define MWIDTH 5632
#define NEXP   8
#define RANK   16
#define ERANK  128
#define FSCALE 2.0f

typedef __half h16;

// ---------------- scratch (uint4 => 16B aligned) ----------------
__device__ uint4 g_xh_[NTOK*DMODEL/8], g_xl_[NTOK*DMODEL/8];          // x hi/lo fp16
__device__ uint4 g_wg_[(size_t)MWIDTH*DMODEL/8];                      // weights fp16
__device__ uint4 g_wu_[(size_t)MWIDTH*DMODEL/8];
__device__ uint4 g_wd_[(size_t)MWIDTH*DMODEL/8];
__device__ uint4 g_hh_[(size_t)NTOK*MWIDTH/8], g_hl_[(size_t)NTOK*MWIDTH/8];
__device__ uint4 g_cgh_[NTOK*ERANK/8], g_cgl_[NTOK*ERANK/8];
__device__ uint4 g_cuh_[NTOK*ERANK/8], g_cul_[NTOK*ERANK/8];
__device__ uint4 g_cdh_[NTOK*ERANK/8], g_cdl_[NTOK*ERANK/8];
__device__ uint4 g_bg_[MWIDTH*ERANK/8], g_bu_[MWIDTH*ERANK/8];        // flat [n][128] fp16
__device__ uint4 g_bd_[DMODEL*ERANK/8];

// ---------------- helpers ----------------
__device__ __forceinline__ uint32_t s2u(const void* p){
    return (uint32_t)__cvta_generic_to_shared(p);
}
__device__ __forceinline__ uint32_t sw128(uint32_t o){ return o ^ ((o >> 3) & 0x70u); }
__device__ __forceinline__ void cp16(uint32_t dst, const void* src){
    asm volatile("cp.async.cg.shared.global [%0], [%1], 16;" :: "r"(dst), "l"(src));
}
__device__ __forceinline__ void cp_commit(){ asm volatile("cp.async.commit_group;" ::: "memory"); }
__device__ __forceinline__ void cp_wait1(){ asm volatile("cp.async.wait_group 1;" ::: "memory"); }

#define LDM4(R, A) asm volatile( \
    "ldmatrix.sync.aligned.m8n8.x4.shared.b16 {%0,%1,%2,%3}, [%4];" \
    : "=r"((R)[0]), "=r"((R)[1]), "=r"((R)[2]), "=r"((R)[3]) : "r"(A))

#define MMA(D, A, B0, B1) asm volatile( \
    "mma.sync.aligned.m16n8k16.row.col.f32.f16.f16.f32 " \
    "{%0,%1,%2,%3}, {%4,%5,%6,%7}, {%8,%9}, {%0,%1,%2,%3};" \
    : "+f"((D)[0]), "+f"((D)[1]), "+f"((D)[2]), "+f"((D)[3]) \
    : "r"((A)[0]), "r"((A)[1]), "r"((A)[2]), "r"((A)[3]), "r"(B0), "r"(B1))

__device__ __forceinline__ void split1h(float v, h16& h, h16& l){
    h = __float2half_rn(v);
    l = __float2half_rn(v - __half2float(h));
}

// ---------------- conversion kernels ----------------
__global__ void k_half(const float* __restrict__ in, h16* __restrict__ o, int n4){
    int i = blockIdx.x * blockDim.x + threadIdx.x;
    if (i >= n4) return;
    float4 v = ((const float4*)in)[i];
    uint2 u;
    __half2 p0 = __floats2half2_rn(v.x, v.y);
    __half2 p1 = __floats2half2_rn(v.z, v.w);
    u.x = *(uint32_t*)&p0; u.y = *(uint32_t*)&p1;
    ((uint2*)o)[i] = u;
}
__global__ void k_split2(const float* __restrict__ in, h16* __restrict__ oh,
                         h16* __restrict__ ol, int n4){
    int i = blockIdx.x * blockDim.x + threadIdx.x;
    if (i >= n4) return;
    float4 v = ((const float4*)in)[i];
    h16 h0,l0,h1,l1,h2,l2,h3,l3;
    split1h(v.x,h0,l0); split1h(v.y,h1,l1); split1h(v.z,h2,l2); split1h(v.w,h3,l3);
    __half2 ph0 = __halves2half2(h0,h1), ph1 = __halves2half2(h2,h3);
    __half2 pl0 = __halves2half2(l0,l1), pl1 = __halves2half2(l2,l3);
    uint2 uh{*(uint32_t*)&ph0, *(uint32_t*)&ph1};
    uint2 ul{*(uint32_t*)&pl0, *(uint32_t*)&pl1};
    ((uint2*)oh)[i] = uh; ((uint2*)ol)[i] = ul;
}
// Bexp [E,N,R] -> flat [N, E*R] fp16
__global__ void k_splitB(const float* __restrict__ in, h16* __restrict__ o, int N){
    int n = blockIdx.x, j = threadIdx.x;           // 128 threads
    int e = j >> 4, r = j & 15;
    o[(size_t)n * ERANK + j] = __float2half_rn(in[((size_t)e * N + n) * RANK + r]);
}

// ---------------- router ----------------
__global__ void k_router(const float* __restrict__ x,  const float* __restrict__ Wr,
                         const float* __restrict__ br, const float* __restrict__ Ag,
                         const float* __restrict__ Au,
                         float* __restrict__ out_routing, float* __restrict__ out_choice)
{
    __shared__ float xs[DMODEL];
    __shared__ float red[40];
    __shared__ float routing_s[NEXP];
    __shared__ int   amax_s;

    const int t = blockIdx.x;
    const float* xrow = x + (size_t)t * DMODEL;
    for (int i = threadIdx.x; i < DMODEL/4; i += blockDim.x)
        ((float4*)xs)[i] = ((const float4*)xrow)[i];
    __syncthreads();

    const int w = threadIdx.x >> 5, lane = threadIdx.x & 31;
    #pragma unroll
    for (int q = 0; q < 5; ++q) {
        const int o = w + 8*q;
        const float* wrow = (o < 8)  ? (Wr + o*DMODEL)
                          : (o < 24) ? (Ag + (o-8)*DMODEL)
                                     : (Au + (o-24)*DMODEL);
        float s = 0.f;
        for (int k = lane; k < DMODEL; k += 32) s = fmaf(xs[k], wrow[k], s);
        #pragma unroll
        for (int off = 16; off; off >>= 1) s += __shfl_xor_sync(0xffffffffu, s, off);
        if (lane == 0) red[o] = s;
    }
    __syncthreads();

    if (threadIdx.x == 0) {
        float lg[NEXP]; float mx = -1e30f;
        #pragma unroll
        for (int e = 0; e < NEXP; ++e){ lg[e] = red[e] + br[e]; mx = fmaxf(mx, lg[e]); }
        float sum = 0.f;
        #pragma unroll
        for (int e = 0; e < NEXP; ++e){ lg[e] = expf(lg[e]-mx); sum += lg[e]; }
        const float inv = 1.f/sum;
        int am = 0; float best = -1.f;
        #pragma unroll
        for (int e = 0; e < NEXP; ++e){
            const float r = lg[e]*inv; routing_s[e] = r;
            if (r > best){ best = r; am = e; }
        }
        amax_s = am;
    }
    __syncthreads();

    if (threadIdx.x < NEXP) {
        const float r = routing_s[threadIdx.x];
        out_routing[t*NEXP + threadIdx.x] = r;
        const float yh = (threadIdx.x == amax_s) ? 1.f : 0.f;
        out_choice[t*NEXP + threadIdx.x] = (yh - r) + r;
    }
    const int j = threadIdx.x & 127;
    const int e = j >> 4, rr = j & 15;
    h16 h, l;
    if (threadIdx.x < 128) {
        split1h(routing_s[e] * red[8 + rr] * FSCALE, h, l);
        ((h16*)g_cgh_)[(size_t)t*ERANK + j] = h;
        ((h16*)g_cgl_)[(size_t)t*ERANK + j] = l;
    } else {
        split1h(routing_s[e] * red[24 + rr] * FSCALE, h, l);
        ((h16*)g_cuh_)[(size_t)t*ERANK + j] = h;
        ((h16*)g_cul_)[(size_t)t*ERANK + j] = l;
    }
}

// ---------------- h @ Ad^T -> c_d ----------------
__global__ void k_hd(const float* __restrict__ Ad, const float* __restrict__ routing)
{
    __shared__ float hs[MWIDTH];
    __shared__ float red[RANK];
    const int t = blockIdx.x;
    const h16* hh = (const h16*)g_hh_ + (size_t)t * MWIDTH;
    const h16* hl = (const h16*)g_hl_ + (size_t)t * MWIDTH;
    for (int i = threadIdx.x; i < MWIDTH; i += blockDim.x)
        hs[i] = __half2float(hh[i]) + __half2float(hl[i]);
    __syncthreads();

    const int w = threadIdx.x >> 5, lane = threadIdx.x & 31;
    #pragma unroll
    for (int q = 0; q < 2; ++q) {
        const int r = w*2 + q;
        const float* arow = Ad + (size_t)r * MWIDTH;
        float s = 0.f;
        for (int k = lane; k < MWIDTH; k += 32) s = fmaf(hs[k], arow[k], s);
        #pragma unroll
        for (int off = 16; off; off >>= 1) s += __shfl_xor_sync(0xffffffffu, s, off);
        if (lane == 0) red[r] = s;
    }
    __syncthreads();
    if (threadIdx.x < 128) {
        const int e = threadIdx.x >> 4, rr = threadIdx.x & 15;
        h16 h, l;
        split1h(routing[t*NEXP + e] * red[rr] * FSCALE, h, l);
        ((h16*)g_cdh_)[(size_t)t*ERANK + threadIdx.x] = h;
        ((h16*)g_cdl_)[(size_t)t*ERANK + threadIdx.x] = l;
    }
}

// ---------------- mma.sync GEMM: BM=128, BN=128, BK=64, 2-pass fp16 ----------------
// DUAL: A=x(hi/lo), B0=Wg, B1=Wu (+aug cg/Bg, cu/Bu), epilogue silu(g)*u -> h planes.
// !DUAL: A=h(hi/lo), B0=Wd (+aug cd/Bd), epilogue -> fp32 out.
template<bool DUAL>
__global__ __launch_bounds__(256, 1)
void k_mma(float* __restrict__ OutP)
{
    constexpr int STAGES = 3;
    constexpr int NPL    = DUAL ? 4 : 3;                 // planes per stage
    constexpr int PLANE  = 16384;                        // 128 rows x 128B
    constexpr int STAGEB = NPL * PLANE;
    constexpr int NKM    = DUAL ? (DMODEL/64) : (MWIDTH/64);  // 32 / 88
    constexpr int NT     = DUAL ? (NKM + 4) : (NKM + 2);

    extern __shared__ __align__(16) char smem[];
    const uint32_t sb = s2u(smem);
    const int tid = threadIdx.x, wid = tid >> 5, lane = tid & 31;
    const int wm = wid & 3, wn = wid >> 2;               // 4 x 2 warp grid
    const int m0 = blockIdx.y * 128, n0 = blockIdx.x * 128;

    float accG[2][8][4];
    float accU[DUAL?2:1][DUAL?8:1][DUAL?4:1];
    #pragma unroll
    for (int m=0;m<2;++m) for (int j=0;j<8;++j) for (int q=0;q<4;++q) accG[m][j][q]=0.f;
    if constexpr (DUAL){
        #pragma unroll
        for (int m=0;m<2;++m) for (int j=0;j<8;++j) for (int q=0;q<4;++q) accU[m][j][q]=0.f;
    }

    auto ldplane = [&](uint32_t dst, const h16* src, int stride, int rbase, int koff){
        #pragma unroll
        for (int it = 0; it < 4; ++it){
            const int id = tid + it*256;                 // 0..1023
            const int row = id >> 3, ch = id & 7;
            cp16(dst + sw128((uint32_t)(row*128 + ch*16)),
                 src + (size_t)(rbase + row)*stride + koff + ch*8);
        }
    };
    auto load_chunk = [&](int kt){
        const uint32_t st = sb + (uint32_t)(kt % STAGES) * STAGEB;
        const h16 *Ah, *Al, *B0, *B1 = nullptr; int str, koff;
        if constexpr (DUAL){
            if (kt < NKM){ Ah=(const h16*)g_xh_;  Al=(const h16*)g_xl_;
                           B0=(const h16*)g_wg_;  B1=(const h16*)g_wu_;
                           str=DMODEL; koff=kt*64; }
            else if (kt < NKM+2){ Ah=(const h16*)g_cgh_; Al=(const h16*)g_cgl_;
                                  B0=(const h16*)g_bg_;  str=ERANK; koff=(kt-NKM)*64; }
            else { Ah=(const h16*)g_cuh_; Al=(const h16*)g_cul_;
                   B0=(const h16*)g_bu_;  str=ERANK; koff=(kt-NKM-2)*64; }
        } else {
            if (kt < NKM){ Ah=(const h16*)g_hh_; Al=(const h16*)g_hl_;
                           B0=(const h16*)g_wd_; str=MWIDTH; koff=kt*64; }
            else { Ah=(const h16*)g_cdh_; Al=(const h16*)g_cdl_;
                   B0=(const h16*)g_bd_;  str=ERANK; koff=(kt-NKM)*64; }
        }
        ldplane(st + 0*PLANE, Ah, str, m0, koff);
        ldplane(st + 1*PLANE, Al, str, m0, koff);
        ldplane(st + 2*PLANE, B0, str, n0, koff);
        if (DUAL && B1) ldplane(st + 3*PLANE, B1, str, n0, koff);
    };
    auto ldaddr = [&](uint32_t pbase, int rbase, int kb) -> uint32_t {
        const int row = rbase + (lane & 15);
        return pbase + sw128((uint32_t)(row*128 + kb + ((lane >> 4) << 4)));
    };

    // prologue: stages 0,1
    load_chunk(0); cp_commit();
    load_chunk(1); cp_commit();

    for (int kt = 0; kt < NT; ++kt){
        cp_wait1();
        __syncthreads();
        const uint32_t st = sb + (uint32_t)(kt % STAGES) * STAGEB;
        const uint32_t pAh = st, pAl = st + PLANE, pB0 = st + 2*PLANE, pB1 = st + 3*PLANE;
        // mode: 0 = main (G [+U]), 1 = G-only aug, 2 = U-only aug
        int mode = 0;
        if constexpr (DUAL){ if (kt >= NKM) mode = (kt < NKM+2) ? 1 : 2; }
        else               { if (kt >= NKM) mode = 1; }

        #pragma unroll
        for (int ks = 0; ks < 4; ++ks){
            const int kb = ks*32;
            uint32_t ah[2][4], al[2][4], bb[4][4];
            LDM4(ah[0], ldaddr(pAh, wm*32,      kb));
            LDM4(ah[1], ldaddr(pAh, wm*32+16,   kb));
            LDM4(al[0], ldaddr(pAl, wm*32,      kb));
            LDM4(al[1], ldaddr(pAl, wm*32+16,   kb));
            #pragma unroll
            for (int g = 0; g < 4; ++g) LDM4(bb[g], ldaddr(pB0, wn*64 + g*16, kb));

            if (mode != 2){
                #pragma unroll
                for (int m = 0; m < 2; ++m)
                    #pragma unroll
                    for (int j = 0; j < 8; ++j){
                        const uint32_t bx = bb[j>>1][j&1], by = bb[j>>1][(j&1)+2];
                        MMA(accG[m][j], ah[m], bx, by);
                        MMA(accG[m][j], al[m], bx, by);
                    }
            }
            if constexpr (DUAL){
                if (mode == 0){
                    #pragma unroll
                    for (int g = 0; g < 4; ++g) LDM4(bb[g], ldaddr(pB1, wn*64 + g*16, kb));
                }
                if (mode != 1){
                    #pragma unroll
                    for (int m = 0; m < 2; ++m)
                        #pragma unroll
                        for (int j = 0; j < 8; ++j){
                            const uint32_t bx = bb[j>>1][j&1], by = bb[j>>1][(j&1)+2];
                            MMA(accU[m][j], ah[m], bx, by);
                            MMA(accU[m][j], al[m], bx, by);
                        }
                }
            }
        }
        __syncthreads();
        if (kt + STAGES - 1 < NT) load_chunk(kt + STAGES - 1);
        cp_commit();
    }

    // ---------------- epilogue ----------------
    #pragma unroll
    for (int m = 0; m < 2; ++m){
        #pragma unroll
        for (int j = 0; j < 8; ++j){
            const int r0 = m0 + wm*32 + m*16 + (lane >> 2);
            const int c0 = n0 + wn*64 + j*8 + (lane & 3)*2;
            if constexpr (DUAL){
                h16* ghh = (h16*)g_hh_; h16* ghl = (h16*)g_hl_;
                float hv[4];
                #pragma unroll
                for (int q = 0; q < 4; ++q){
                    const float g = accG[m][j][q], u = accU[m][j][q];
                    hv[q] = g * u / (1.f + __expf(-g));
                }
                h16 ha,la,hb,lb;
                split1h(hv[0], ha, la); split1h(hv[1], hb, lb);
                *(__half2*)(ghh + (size_t)r0*MWIDTH + c0) = __halves2half2(ha, hb);
                *(__half2*)(ghl + (size_t)r0*MWIDTH + c0) = __halves2half2(la, lb);
                split1h(hv[2], ha, la); split1h(hv[3], hb, lb);
                *(__half2*)(ghh + (size_t)(r0+8)*MWIDTH + c0) = __halves2half2(ha, hb);
                *(__half2*)(ghl + (size_t)(r0+8)*MWIDTH + c0) = __halves2half2(la, lb);
            } else {
                *(float2*)(OutP + (size_t)r0*DMODEL + c0)
                    = make_float2(accG[m][j][0], accG[m][j][1]);
                *(float2*)(OutP + (size_t)(r0+8)*DMODEL + c0)
                    = make_float2(accG[m][j][2], accG[m][j][3]);
            }
        }
    }
}

// ---------------------------------------------------------------------------
extern "C" void kernel_launch(void* const* d_in, const int* in_sizes, int n_in,
                              void* d_out, int out_size)
{
    const float* x  = (const float*)d_in[0];
    const float* Wr = (const float*)d_in[1];
    const float* br = (const float*)d_in[2];
    const float* Wg = (const float*)d_in[3];
    const float* Wu = (const float*)d_in[4];
    const float* Wd = (const float*)d_in[5];
    const float* Ag = (const float*)d_in[6];
    const float* Au = (const float*)d_in[7];
    const float* Ad = (const float*)d_in[8];
    const float* Bg = (const float*)d_in[9];
    const float* Bu = (const float*)d_in[10];
    const float* Bd = (const float*)d_in[11];

    float* out     = (float*)d_out;
    float* routing = out + (size_t)NTOK * DMODEL;
    float* choice  = routing + NTOK * NEXP;

    void *xh,*xl,*wg,*wu,*wd,*bg,*bu,*bd;
    cudaGetSymbolAddress(&xh, g_xh_); cudaGetSymbolAddress(&xl, g_xl_);
    cudaGetSymbolAddress(&wg, g_wg_); cudaGetSymbolAddress(&wu, g_wu_);
    cudaGetSymbolAddress(&wd, g_wd_);
    cudaGetSymbolAddress(&bg, g_bg_); cudaGetSymbolAddress(&bu, g_bu_);
    cudaGetSymbolAddress(&bd, g_bd_);

    const int n4x = NTOK*DMODEL/4, n4w = MWIDTH*DMODEL/4;
    k_split2<<<(n4x+255)/256, 256>>>(x, (h16*)xh, (h16*)xl, n4x);
    k_half<<<(n4w+255)/256, 256>>>(Wg, (h16*)wg, n4w);
    k_half<<<(n4w+255)/256, 256>>>(Wu, (h16*)wu, n4w);
    k_half<<<(n4w+255)/256, 256>>>(Wd, (h16*)wd, n4w);
    k_splitB<<<MWIDTH, 128>>>(Bg, (h16*)bg, MWIDTH);
    k_splitB<<<MWIDTH, 128>>>(Bu, (h16*)bu, MWIDTH);
    k_splitB<<<DMODEL, 128>>>(Bd, (h16*)bd, DMODEL);

    k_router<<<NTOK, 256>>>(x, Wr, br, Ag, Au, routing, choice);

    const int smem_dual   = 3 * 4 * 16384;   // 196608
    const int smem_single = 3 * 3 * 16384;   // 147456
    cudaFuncSetAttribute(k_mma<true>,  cudaFuncAttributeMaxDynamicSharedMemorySize, smem_dual);
    cudaFuncSetAttribute(k_mma<false>, cudaFuncAttributeMaxDynamicSharedMemorySize, smem_single);

    k_mma<true><<<dim3(MWIDTH/128, NTOK/128), 256, smem_dual>>>(nullptr);
    k_hd<<<NTOK, 256>>>(Ad, routing);
    k_mma<false><<<dim3(DMODEL/128, NTOK/128), 256, smem_single>>>(out);
}

// round 5
// speedup vs baseline: 6.6921x; 1.9311x over previous
#include <cuda_runtime.h>
#include <cuda_fp16.h>
#include <math.h>
#include <stdint.h>

#define NTOK   4096
#define DMODEL 2048
#define MWIDTH 5632
#define NEXP   8
#define RANK   16
#define ERANK  128
#define FSCALE 2.0f

typedef __half h16;

// ---------------- scratch (uint4 => 16B aligned) ----------------
__device__ uint4 g_x_ [(size_t)NTOK*DMODEL/8];                        // x fp16
__device__ uint4 g_wg_[(size_t)MWIDTH*DMODEL/8];
__device__ uint4 g_wu_[(size_t)MWIDTH*DMODEL/8];
__device__ uint4 g_wd_[(size_t)MWIDTH*DMODEL/8];
__device__ uint4 g_h_ [(size_t)NTOK*MWIDTH/8];                        // h fp16
__device__ uint4 g_cg_[NTOK*ERANK/8], g_cu_[NTOK*ERANK/8], g_cd_[NTOK*ERANK/8];
__device__ uint4 g_bg_[MWIDTH*ERANK/8], g_bu_[MWIDTH*ERANK/8];        // flat [n][128]
__device__ uint4 g_bd_[DMODEL*ERANK/8];

// ---------------- helpers ----------------
__device__ __forceinline__ uint32_t s2u(const void* p){
    return (uint32_t)__cvta_generic_to_shared(p);
}
__device__ __forceinline__ uint32_t sw128(uint32_t o){ return o ^ ((o >> 3) & 0x70u); }
__device__ __forceinline__ void cp16(uint32_t dst, const void* src){
    asm volatile("cp.async.cg.shared.global [%0], [%1], 16;" :: "r"(dst), "l"(src));
}
__device__ __forceinline__ void cp_commit(){ asm volatile("cp.async.commit_group;" ::: "memory"); }
__device__ __forceinline__ void cp_wait1(){ asm volatile("cp.async.wait_group 1;" ::: "memory"); }

#define LDM4(R, A) asm volatile( \
    "ldmatrix.sync.aligned.m8n8.x4.shared.b16 {%0,%1,%2,%3}, [%4];" \
    : "=r"((R)[0]), "=r"((R)[1]), "=r"((R)[2]), "=r"((R)[3]) : "r"(A))

#define MMA(D, A0, A1, A2, A3, B0, B1) asm volatile( \
    "mma.sync.aligned.m16n8k16.row.col.f32.f16.f16.f32 " \
    "{%0,%1,%2,%3}, {%4,%5,%6,%7}, {%8,%9}, {%0,%1,%2,%3};" \
    : "+f"((D)[0]), "+f"((D)[1]), "+f"((D)[2]), "+f"((D)[3]) \
    : "r"(A0), "r"(A1), "r"(A2), "r"(A3), "r"(B0), "r"(B1))

// ---------------- conversion kernels ----------------
__global__ void k_half(const float* __restrict__ in, h16* __restrict__ o, int n4){
    int i = blockIdx.x * blockDim.x + threadIdx.x;
    if (i >= n4) return;
    float4 v = ((const float4*)in)[i];
    __half2 p0 = __floats2half2_rn(v.x, v.y);
    __half2 p1 = __floats2half2_rn(v.z, v.w);
    uint2 u{*(uint32_t*)&p0, *(uint32_t*)&p1};
    ((uint2*)o)[i] = u;
}
// Bexp [E,N,R] -> flat [N, E*R] fp16
__global__ void k_splitB(const float* __restrict__ in, h16* __restrict__ o, int N){
    int n = blockIdx.x, j = threadIdx.x;           // 128 threads
    int e = j >> 4, r = j & 15;
    o[(size_t)n * ERANK + j] = __float2half_rn(in[((size_t)e * N + n) * RANK + r]);
}

// ---------------- router ----------------
__global__ void k_router(const float* __restrict__ x,  const float* __restrict__ Wr,
                         const float* __restrict__ br, const float* __restrict__ Ag,
                         const float* __restrict__ Au,
                         float* __restrict__ out_routing, float* __restrict__ out_choice)
{
    __shared__ float xs[DMODEL];
    __shared__ float red[40];
    __shared__ float routing_s[NEXP];
    __shared__ int   amax_s;

    const int t = blockIdx.x;
    const float* xrow = x + (size_t)t * DMODEL;
    for (int i = threadIdx.x; i < DMODEL/4; i += blockDim.x)
        ((float4*)xs)[i] = ((const float4*)xrow)[i];
    __syncthreads();

    const int w = threadIdx.x >> 5, lane = threadIdx.x & 31;
    #pragma unroll
    for (int q = 0; q < 5; ++q) {
        const int o = w + 8*q;
        const float* wrow = (o < 8)  ? (Wr + o*DMODEL)
                          : (o < 24) ? (Ag + (o-8)*DMODEL)
                                     : (Au + (o-24)*DMODEL);
        float s = 0.f;
        for (int k = lane; k < DMODEL; k += 32) s = fmaf(xs[k], wrow[k], s);
        #pragma unroll
        for (int off = 16; off; off >>= 1) s += __shfl_xor_sync(0xffffffffu, s, off);
        if (lane == 0) red[o] = s;
    }
    __syncthreads();

    if (threadIdx.x == 0) {
        float lg[NEXP]; float mx = -1e30f;
        #pragma unroll
        for (int e = 0; e < NEXP; ++e){ lg[e] = red[e] + br[e]; mx = fmaxf(mx, lg[e]); }
        float sum = 0.f;
        #pragma unroll
        for (int e = 0; e < NEXP; ++e){ lg[e] = expf(lg[e]-mx); sum += lg[e]; }
        const float inv = 1.f/sum;
        int am = 0; float best = -1.f;
        #pragma unroll
        for (int e = 0; e < NEXP; ++e){
            const float r = lg[e]*inv; routing_s[e] = r;
            if (r > best){ best = r; am = e; }
        }
        amax_s = am;
    }
    __syncthreads();

    if (threadIdx.x < NEXP) {
        const float r = routing_s[threadIdx.x];
        out_routing[t*NEXP + threadIdx.x] = r;
        const float yh = (threadIdx.x == amax_s) ? 1.f : 0.f;
        out_choice[t*NEXP + threadIdx.x] = (yh - r) + r;
    }
    const int j = threadIdx.x & 127;
    const int e = j >> 4, rr = j & 15;
    if (threadIdx.x < 128)
        ((h16*)g_cg_)[(size_t)t*ERANK + j] = __float2half_rn(routing_s[e]*red[8+rr]*FSCALE);
    else
        ((h16*)g_cu_)[(size_t)t*ERANK + j] = __float2half_rn(routing_s[e]*red[24+rr]*FSCALE);
}

// ---------------- h @ Ad^T -> c_d ----------------
__global__ void k_hd(const float* __restrict__ Ad, const float* __restrict__ routing)
{
    __shared__ float hs[MWIDTH];
    __shared__ float red[RANK];
    const int t = blockIdx.x;
    const h16* hrow = (const h16*)g_h_ + (size_t)t * MWIDTH;
    for (int i = threadIdx.x; i < MWIDTH/2; i += blockDim.x){
        __half2 v = ((const __half2*)hrow)[i];
        float2 f = __half22float2(v);
        hs[2*i] = f.x; hs[2*i+1] = f.y;
    }
    __syncthreads();

    const int w = threadIdx.x >> 5, lane = threadIdx.x & 31;
    #pragma unroll
    for (int q = 0; q < 2; ++q) {
        const int r = w*2 + q;
        const float* arow = Ad + (size_t)r * MWIDTH;
        float s = 0.f;
        for (int k = lane; k < MWIDTH; k += 32) s = fmaf(hs[k], arow[k], s);
        #pragma unroll
        for (int off = 16; off; off >>= 1) s += __shfl_xor_sync(0xffffffffu, s, off);
        if (lane == 0) red[r] = s;
    }
    __syncthreads();
    if (threadIdx.x < 128) {
        const int e = threadIdx.x >> 4, rr = threadIdx.x & 15;
        ((h16*)g_cd_)[(size_t)t*ERANK + threadIdx.x]
            = __float2half_rn(routing[t*NEXP + e] * red[rr] * FSCALE);
    }
}

// ---------------- single-pass fp16 mma.sync GEMM, 2 CTAs/SM ----------------
// DUAL : BM=128 BN=64,  A=x,  B0=Wg->accG, B1=Wu->accU (+aug cg/Bg, cu/Bu),
//        epilogue silu(g)*u -> g_h_ (fp16)
// !DUAL: BM=128 BN=128, A=h,  B0=Wd (+aug cd/Bd), epilogue -> fp32 out
template<bool DUAL>
__global__ __launch_bounds__(256, 2)
void k_mma(float* __restrict__ OutP)
{
    constexpr int STAGES = 3;
    constexpr int PA     = 16384;                       // A plane: 128 rows x 128B
    constexpr int PB     = DUAL ? 8192 : 16384;         // B plane
    constexpr int STAGEB = PA + (DUAL ? 2 : 1) * PB;    // 32KB either way
    constexpr int BN     = DUAL ? 64 : 128;
    constexpr int JN     = DUAL ? 4 : 8;                // 8-col groups per warp n-tile
    constexpr int WTN    = DUAL ? 32 : 64;
    constexpr int NKM    = DUAL ? (DMODEL/64) : (MWIDTH/64);  // 32 / 88
    constexpr int NT     = DUAL ? (NKM + 4) : (NKM + 2);

    extern __shared__ __align__(16) char smem[];
    const uint32_t sb = s2u(smem);
    const int tid = threadIdx.x, wid = tid >> 5, lane = tid & 31;
    const int wm = wid & 3, wn = wid >> 2;
    const int m0 = blockIdx.y * 128, n0 = blockIdx.x * BN;

    float accG[2][JN][4];
    float accU[DUAL?2:1][DUAL?JN:1][4];
    #pragma unroll
    for (int m=0;m<2;++m) for (int j=0;j<JN;++j) for (int q=0;q<4;++q) accG[m][j][q]=0.f;
    if constexpr (DUAL){
        #pragma unroll
        for (int m=0;m<2;++m) for (int j=0;j<JN;++j) for (int q=0;q<4;++q) accU[m][j][q]=0.f;
    }

    auto ldplane = [&](uint32_t dst, const h16* src, int stride, int rbase,
                       int koff, int nrows){
        for (int it = 0; it < nrows/32; ++it){
            const int id = tid + it*256;
            const int row = id >> 3, ch = id & 7;
            cp16(dst + sw128((uint32_t)(row*128 + ch*16)),
                 src + (size_t)(rbase + row)*stride + koff + ch*8);
        }
    };
    auto load_chunk = [&](int kt){
        const uint32_t st = sb + (uint32_t)(kt % STAGES) * STAGEB;
        if constexpr (DUAL){
            if (kt < NKM){
                ldplane(st,       (const h16*)g_x_,  DMODEL, m0, kt*64, 128);
                ldplane(st+PA,    (const h16*)g_wg_, DMODEL, n0, kt*64, 64);
                ldplane(st+PA+PB, (const h16*)g_wu_, DMODEL, n0, kt*64, 64);
            } else {
                const bool gsel = kt < NKM+2;
                const int ko = (kt - NKM - (gsel ? 0 : 2)) * 64;
                ldplane(st,    gsel ? (const h16*)g_cg_ : (const h16*)g_cu_, ERANK, m0, ko, 128);
                ldplane(st+PA, gsel ? (const h16*)g_bg_ : (const h16*)g_bu_, ERANK, n0, ko, 64);
            }
        } else {
            if (kt < NKM){
                ldplane(st,    (const h16*)g_h_,  MWIDTH, m0, kt*64, 128);
                ldplane(st+PA, (const h16*)g_wd_, MWIDTH, n0, kt*64, 128);
            } else {
                const int ko = (kt - NKM) * 64;
                ldplane(st,    (const h16*)g_cd_, ERANK, m0, ko, 128);
                ldplane(st+PA, (const h16*)g_bd_, ERANK, n0, ko, 128);
            }
        }
        cp_commit();
    };
    auto ldaddr = [&](uint32_t pbase, int rbase, int kb) -> uint32_t {
        const int row = rbase + (lane & 15);
        return pbase + sw128((uint32_t)(row*128 + kb + ((lane >> 4) << 4)));
    };

    load_chunk(0);
    load_chunk(1);

    for (int kt = 0; kt < NT; ++kt){
        cp_wait1();
        __syncthreads();
        const uint32_t st = sb + (uint32_t)(kt % STAGES) * STAGEB;
        // mode: 0 main, 1 aug->accG, 2 aug->accU
        int mode = 0;
        if (kt >= NKM) mode = (DUAL && kt >= NKM+2) ? 2 : 1;

        #pragma unroll
        for (int ks = 0; ks < 4; ++ks){
            const int kb = ks*32;
            uint32_t a0[4], a1[4], bb[JN/2][4];
            LDM4(a0, ldaddr(st, wm*32,    kb));
            LDM4(a1, ldaddr(st, wm*32+16, kb));
            #pragma unroll
            for (int g = 0; g < JN/2; ++g)
                LDM4(bb[g], ldaddr(st+PA, wn*WTN + g*16, kb));

            if (mode != 2){
                #pragma unroll
                for (int j = 0; j < JN; ++j){
                    const uint32_t bx = bb[j>>1][j&1], by = bb[j>>1][(j&1)+2];
                    MMA(accG[0][j], a0[0],a0[1],a0[2],a0[3], bx, by);
                    MMA(accG[1][j], a1[0],a1[1],a1[2],a1[3], bx, by);
                }
            } else {
                #pragma unroll
                for (int j = 0; j < JN; ++j){
                    const uint32_t bx = bb[j>>1][j&1], by = bb[j>>1][(j&1)+2];
                    MMA(accU[0][j], a0[0],a0[1],a0[2],a0[3], bx, by);
                    MMA(accU[1][j], a1[0],a1[1],a1[2],a1[3], bx, by);
                }
            }
            if constexpr (DUAL){
                if (mode == 0){
                    #pragma unroll
                    for (int g = 0; g < JN/2; ++g)
                        LDM4(bb[g], ldaddr(st+PA+PB, wn*WTN + g*16, kb));
                    #pragma unroll
                    for (int j = 0; j < JN; ++j){
                        const uint32_t bx = bb[j>>1][j&1], by = bb[j>>1][(j&1)+2];
                        MMA(accU[0][j], a0[0],a0[1],a0[2],a0[3], bx, by);
                        MMA(accU[1][j], a1[0],a1[1],a1[2],a1[3], bx, by);
                    }
                }
            }
        }
        __syncthreads();
        if (kt + STAGES - 1 < NT) load_chunk(kt + STAGES - 1);
    }

    // ---------------- epilogue ----------------
    #pragma unroll
    for (int m = 0; m < 2; ++m){
        #pragma unroll
        for (int j = 0; j < JN; ++j){
            const int r0 = m0 + wm*32 + m*16 + (lane >> 2);
            const int c0 = n0 + wn*WTN + j*8 + (lane & 3)*2;
            if constexpr (DUAL){
                h16* gh = (h16*)g_h_;
                float hv[4];
                #pragma unroll
                for (int q = 0; q < 4; ++q){
                    const float g = accG[m][j][q], u = accU[m][j][q];
                    hv[q] = g * u / (1.f + __expf(-g));
                }
                *(__half2*)(gh + (size_t)r0*MWIDTH + c0)     = __floats2half2_rn(hv[0], hv[1]);
                *(__half2*)(gh + (size_t)(r0+8)*MWIDTH + c0) = __floats2half2_rn(hv[2], hv[3]);
            } else {
                *(float2*)(OutP + (size_t)r0*DMODEL + c0)
                    = make_float2(accG[m][j][0], accG[m][j][1]);
                *(float2*)(OutP + (size_t)(r0+8)*DMODEL + c0)
                    = make_float2(accG[m][j][2], accG[m][j][3]);
            }
        }
    }
}

// ---------------------------------------------------------------------------
extern "C" void kernel_launch(void* const* d_in, const int* in_sizes, int n_in,
                              void* d_out, int out_size)
{
    const float* x  = (const float*)d_in[0];
    const float* Wr = (const float*)d_in[1];
    const float* br = (const float*)d_in[2];
    const float* Wg = (const float*)d_in[3];
    const float* Wu = (const float*)d_in[4];
    const float* Wd = (const float*)d_in[5];
    const float* Ag = (const float*)d_in[6];
    const float* Au = (const float*)d_in[7];
    const float* Ad = (const float*)d_in[8];
    const float* Bg = (const float*)d_in[9];
    const float* Bu = (const float*)d_in[10];
    const float* Bd = (const float*)d_in[11];

    float* out     = (float*)d_out;
    float* routing = out + (size_t)NTOK * DMODEL;
    float* choice  = routing + NTOK * NEXP;

    void *xp,*wg,*wu,*wd,*bg,*bu,*bd;
    cudaGetSymbolAddress(&xp, g_x_);
    cudaGetSymbolAddress(&wg, g_wg_); cudaGetSymbolAddress(&wu, g_wu_);
    cudaGetSymbolAddress(&wd, g_wd_);
    cudaGetSymbolAddress(&bg, g_bg_); cudaGetSymbolAddress(&bu, g_bu_);
    cudaGetSymbolAddress(&bd, g_bd_);

    const int n4x = NTOK*DMODEL/4, n4w = MWIDTH*DMODEL/4;
    k_half<<<(n4x+255)/256, 256>>>(x,  (h16*)xp, n4x);
    k_half<<<(n4w+255)/256, 256>>>(Wg, (h16*)wg, n4w);
    k_half<<<(n4w+255)/256, 256>>>(Wu, (h16*)wu, n4w);
    k_half<<<(n4w+255)/256, 256>>>(Wd, (h16*)wd, n4w);
    k_splitB<<<MWIDTH, 128>>>(Bg, (h16*)bg, MWIDTH);
    k_splitB<<<MWIDTH, 128>>>(Bu, (h16*)bu, MWIDTH);
    k_splitB<<<DMODEL, 128>>>(Bd, (h16*)bd, DMODEL);

    k_router<<<NTOK, 256>>>(x, Wr, br, Ag, Au, routing, choice);

    const int smem_sz = 3 * 32768;   // 98304 both variants
    cudaFuncSetAttribute(k_mma<true>,  cudaFuncAttributeMaxDynamicSharedMemorySize, smem_sz);
    cudaFuncSetAttribute(k_mma<false>, cudaFuncAttributeMaxDynamicSharedMemorySize, smem_sz);

    k_mma<true><<<dim3(MWIDTH/64, NTOK/128), 256, smem_sz>>>(nullptr);
    k_hd<<<NTOK, 256>>>(Ad, routing);
    k_mma<false><<<dim3(DMODEL/128, NTOK/128), 256, smem_sz>>>(out);
}

// round 7
// speedup vs baseline: 6.8174x; 1.0187x over previous
#include <cuda_runtime.h>
#include <cuda_fp16.h>
#include <math.h>
#include <stdint.h>

#define NTOK   4096
#define DMODEL 2048
#define MWIDTH 5632
#define NEXP   8
#define RANK   16
#define ERANK  128
#define FSCALE 2.0f

typedef __half h16;

// ---------------- scratch (uint4 => 16B aligned) ----------------
__device__ uint4 g_x_ [(size_t)NTOK*DMODEL/8];                        // x fp16
__device__ uint4 g_wg_[(size_t)MWIDTH*DMODEL/8];
__device__ uint4 g_wu_[(size_t)MWIDTH*DMODEL/8];
__device__ uint4 g_wd_[(size_t)MWIDTH*DMODEL/8];
__device__ uint4 g_h_ [(size_t)NTOK*MWIDTH/8];                        // h fp16
__device__ uint4 g_cg_[NTOK*ERANK/8], g_cu_[NTOK*ERANK/8], g_cd_[NTOK*ERANK/8];
__device__ uint4 g_bg_[MWIDTH*ERANK/8], g_bu_[MWIDTH*ERANK/8];        // flat [n][128]
__device__ uint4 g_bd_[DMODEL*ERANK/8];

// ---------------- helpers ----------------
__device__ __forceinline__ uint32_t s2u(const void* p){
    return (uint32_t)__cvta_generic_to_shared(p);
}
__device__ __forceinline__ uint32_t sw128(uint32_t o){ return o ^ ((o >> 3) & 0x70u); }
__device__ __forceinline__ void cp16(uint32_t dst, const void* src){
    asm volatile("cp.async.cg.shared.global [%0], [%1], 16;" :: "r"(dst), "l"(src));
}
__device__ __forceinline__ void cp_commit(){ asm volatile("cp.async.commit_group;" ::: "memory"); }
__device__ __forceinline__ void cp_wait1(){ asm volatile("cp.async.wait_group 1;" ::: "memory"); }

#define LDM4(R, A) asm volatile( \
    "ldmatrix.sync.aligned.m8n8.x4.shared.b16 {%0,%1,%2,%3}, [%4];" \
    : "=r"((R)[0]), "=r"((R)[1]), "=r"((R)[2]), "=r"((R)[3]) : "r"(A))

#define MMA(D, A0, A1, A2, A3, B0, B1) asm volatile( \
    "mma.sync.aligned.m16n8k16.row.col.f32.f16.f16.f32 " \
    "{%0,%1,%2,%3}, {%4,%5,%6,%7}, {%8,%9}, {%0,%1,%2,%3};" \
    : "+f"((D)[0]), "+f"((D)[1]), "+f"((D)[2]), "+f"((D)[3]) \
    : "r"(A0), "r"(A1), "r"(A2), "r"(A3), "r"(B0), "r"(B1))

// ---------------- conversion kernels ----------------
__global__ void k_half(const float* __restrict__ in, h16* __restrict__ o, int n4){
    int i = blockIdx.x * blockDim.x + threadIdx.x;
    if (i >= n4) return;
    float4 v = ((const float4*)in)[i];
    __half2 p0 = __floats2half2_rn(v.x, v.y);
    __half2 p1 = __floats2half2_rn(v.z, v.w);
    uint2 u{*(uint32_t*)&p0, *(uint32_t*)&p1};
    ((uint2*)o)[i] = u;
}
__global__ void k_half3(const float* __restrict__ i0, h16* __restrict__ o0,
                        const float* __restrict__ i1, h16* __restrict__ o1,
                        const float* __restrict__ i2, h16* __restrict__ o2, int n4){
    const float* in = (blockIdx.y == 0) ? i0 : (blockIdx.y == 1) ? i1 : i2;
    h16*         o  = (blockIdx.y == 0) ? o0 : (blockIdx.y == 1) ? o1 : o2;
    int i = blockIdx.x * blockDim.x + threadIdx.x;
    if (i >= n4) return;
    float4 v = ((const float4*)in)[i];
    __half2 p0 = __floats2half2_rn(v.x, v.y);
    __half2 p1 = __floats2half2_rn(v.z, v.w);
    uint2 u{*(uint32_t*)&p0, *(uint32_t*)&p1};
    ((uint2*)o)[i] = u;
}
// Bexp [E,N,R] -> flat [N, E*R] fp16 ; blockIdx.y selects gate/up pair
__global__ void k_splitB2(const float* __restrict__ i0, h16* __restrict__ o0,
                          const float* __restrict__ i1, h16* __restrict__ o1, int N){
    const float* in = blockIdx.y ? i1 : i0;
    h16*         o  = blockIdx.y ? o1 : o0;
    int n = blockIdx.x, j = threadIdx.x;           // 128 threads
    int e = j >> 4, r = j & 15;
    o[(size_t)n * ERANK + j] = __float2half_rn(in[((size_t)e * N + n) * RANK + r]);
}
__global__ void k_splitB(const float* __restrict__ in, h16* __restrict__ o, int N){
    int n = blockIdx.x, j = threadIdx.x;
    int e = j >> 4, r = j & 15;
    o[(size_t)n * ERANK + j] = __float2half_rn(in[((size_t)e * N + n) * RANK + r]);
}

// ---------------- router ----------------
__global__ void k_router(const float* __restrict__ x,  const float* __restrict__ Wr,
                         const float* __restrict__ br, const float* __restrict__ Ag,
                         const float* __restrict__ Au,
                         float* __restrict__ out_routing, float* __restrict__ out_choice)
{
    __shared__ float xs[DMODEL];
    __shared__ float red[40];
    __shared__ float routing_s[NEXP];
    __shared__ int   amax_s;

    const int t = blockIdx.x;
    const float* xrow = x + (size_t)t * DMODEL;
    for (int i = threadIdx.x; i < DMODEL/4; i += blockDim.x)
        ((float4*)xs)[i] = ((const float4*)xrow)[i];
    __syncthreads();

    const int w = threadIdx.x >> 5, lane = threadIdx.x & 31;
    #pragma unroll
    for (int q = 0; q < 5; ++q) {
        const int o = w + 8*q;
        const float* wrow = (o < 8)  ? (Wr + o*DMODEL)
                          : (o < 24) ? (Ag + (o-8)*DMODEL)
                                     : (Au + (o-24)*DMODEL);
        float s = 0.f;
        for (int k = lane; k < DMODEL; k += 32) s = fmaf(xs[k], wrow[k], s);
        #pragma unroll
        for (int off = 16; off; off >>= 1) s += __shfl_xor_sync(0xffffffffu, s, off);
        if (lane == 0) red[o] = s;
    }
    __syncthreads();

    if (threadIdx.x == 0) {
        float lg[NEXP]; float mx = -1e30f;
        #pragma unroll
        for (int e = 0; e < NEXP; ++e){ lg[e] = red[e] + br[e]; mx = fmaxf(mx, lg[e]); }
        float sum = 0.f;
        #pragma unroll
        for (int e = 0; e < NEXP; ++e){ lg[e] = expf(lg[e]-mx); sum += lg[e]; }
        const float inv = 1.f/sum;
        int am = 0; float best = -1.f;
        #pragma unroll
        for (int e = 0; e < NEXP; ++e){
            const float r = lg[e]*inv; routing_s[e] = r;
            if (r > best){ best = r; am = e; }
        }
        amax_s = am;
    }
    __syncthreads();

    if (threadIdx.x < NEXP) {
        const float r = routing_s[threadIdx.x];
        out_routing[t*NEXP + threadIdx.x] = r;
        const float yh = (threadIdx.x == amax_s) ? 1.f : 0.f;
        out_choice[t*NEXP + threadIdx.x] = (yh - r) + r;
    }
    const int j = threadIdx.x & 127;
    const int e = j >> 4, rr = j & 15;
    if (threadIdx.x < 128)
        ((h16*)g_cg_)[(size_t)t*ERANK + j] = __float2half_rn(routing_s[e]*red[8+rr]*FSCALE);
    else
        ((h16*)g_cu_)[(size_t)t*ERANK + j] = __float2half_rn(routing_s[e]*red[24+rr]*FSCALE);
}

// ---------------- h @ Ad^T -> c_d ----------------
__global__ void k_hd(const float* __restrict__ Ad, const float* __restrict__ routing)
{
    __shared__ float hs[MWIDTH];
    __shared__ float red[RANK];
    const int t = blockIdx.x;
    const h16* hrow = (const h16*)g_h_ + (size_t)t * MWIDTH;
    for (int i = threadIdx.x; i < MWIDTH/2; i += blockDim.x){
        __half2 v = ((const __half2*)hrow)[i];
        float2 f = __half22float2(v);
        hs[2*i] = f.x; hs[2*i+1] = f.y;
    }
    __syncthreads();

    const int w = threadIdx.x >> 5, lane = threadIdx.x & 31;
    #pragma unroll
    for (int q = 0; q < 2; ++q) {
        const int r = w*2 + q;
        const float* arow = Ad + (size_t)r * MWIDTH;
        float s = 0.f;
        for (int k = lane; k < MWIDTH; k += 32) s = fmaf(hs[k], arow[k], s);
        #pragma unroll
        for (int off = 16; off; off >>= 1) s += __shfl_xor_sync(0xffffffffu, s, off);
        if (lane == 0) red[r] = s;
    }
    __syncthreads();
    if (threadIdx.x < 128) {
        const int e = threadIdx.x >> 4, rr = threadIdx.x & 15;
        ((h16*)g_cd_)[(size_t)t*ERANK + threadIdx.x]
            = __float2half_rn(routing[t*NEXP + e] * red[rr] * FSCALE);
    }
}

// ---------------- single-pass fp16 mma.sync GEMM, 2 CTAs/SM ----------------
// Mainloop: wait_group 1 -> single __syncthreads -> issue loads(kt+2) -> MMAs.
// DUAL : BM=128 BN=64,  A=x,  B0=Wg->accG, B1=Wu->accU (+aug cg/Bg, cu/Bu),
//        epilogue silu(g)*u -> g_h_ (fp16)
// !DUAL: BM=128 BN=128, A=h,  B0=Wd (+aug cd/Bd), epilogue -> fp32 out
template<bool DUAL>
__global__ __launch_bounds__(256, 2)
void k_mma(float* __restrict__ OutP)
{
    constexpr int STAGES = 3;
    constexpr int PA     = 16384;                       // A plane: 128 rows x 128B
    constexpr int PB     = DUAL ? 8192 : 16384;         // B plane
    constexpr int STAGEB = PA + (DUAL ? 2 : 1) * PB;    // 32KB either way
    constexpr int BN     = DUAL ? 64 : 128;
    constexpr int JN     = DUAL ? 4 : 8;                // 8-col groups per warp n-tile
    constexpr int WTN    = DUAL ? 32 : 64;
    constexpr int NKM    = DUAL ? (DMODEL/64) : (MWIDTH/64);  // 32 / 88
    constexpr int NT     = DUAL ? (NKM + 4) : (NKM + 2);

    extern __shared__ __align__(16) char smem[];
    const uint32_t sb = s2u(smem);
    const int tid = threadIdx.x, wid = tid >> 5, lane = tid & 31;
    const int wm = wid & 3, wn = wid >> 2;
    const int m0 = blockIdx.y * 128, n0 = blockIdx.x * BN;

    float accG[2][JN][4];
    float accU[DUAL?2:1][DUAL?JN:1][4];
    #pragma unroll
    for (int m=0;m<2;++m) for (int j=0;j<JN;++j) for (int q=0;q<4;++q) accG[m][j][q]=0.f;
    if constexpr (DUAL){
        #pragma unroll
        for (int m=0;m<2;++m) for (int j=0;j<JN;++j) for (int q=0;q<4;++q) accU[m][j][q]=0.f;
    }

    auto ldplane = [&](uint32_t dst, const h16* src, int stride, int rbase,
                       int koff, int nrows){
        for (int it = 0; it < nrows/32; ++it){
            const int id = tid + it*256;
            const int row = id >> 3, ch = id & 7;
            cp16(dst + sw128((uint32_t)(row*128 + ch*16)),
                 src + (size_t)(rbase + row)*stride + koff + ch*8);
        }
    };
    auto load_chunk = [&](int kt){
        const uint32_t st = sb + (uint32_t)(kt % STAGES) * STAGEB;
        if constexpr (DUAL){
            if (kt < NKM){
                ldplane(st,       (const h16*)g_x_,  DMODEL, m0, kt*64, 128);
                ldplane(st+PA,    (const h16*)g_wg_, DMODEL, n0, kt*64, 64);
                ldplane(st+PA+PB, (const h16*)g_wu_, DMODEL, n0, kt*64, 64);
            } else {
                const bool gsel = kt < NKM+2;
                const int ko = (kt - NKM - (gsel ? 0 : 2)) * 64;
                ldplane(st,    gsel ? (const h16*)g_cg_ : (const h16*)g_cu_, ERANK, m0, ko, 128);
                ldplane(st+PA, gsel ? (const h16*)g_bg_ : (const h16*)g_bu_, ERANK, n0, ko, 64);
            }
        } else {
            if (kt < NKM){
                ldplane(st,    (const h16*)g_h_,  MWIDTH, m0, kt*64, 128);
                ldplane(st+PA, (const h16*)g_wd_, MWIDTH, n0, kt*64, 128);
            } else {
                const int ko = (kt - NKM) * 64;
                ldplane(st,    (const h16*)g_cd_, ERANK, m0, ko, 128);
                ldplane(st+PA, (const h16*)g_bd_, ERANK, n0, ko, 128);
            }
        }
        cp_commit();
    };
    auto ldaddr = [&](uint32_t pbase, int rbase, int kb) -> uint32_t {
        const int row = rbase + (lane & 15);
        return pbase + sw128((uint32_t)(row*128 + kb + ((lane >> 4) << 4)));
    };

    load_chunk(0);
    load_chunk(1);

    for (int kt = 0; kt < NT; ++kt){
        // Issued so far: tiles 0..kt+1. <=1 pending  =>  tile kt complete.
        cp_wait1();
        __syncthreads();                      // stage kt visible to all warps; all
                                              // reads of stage (kt-1)%3 are done.
        if (kt + 2 < NT) load_chunk(kt + 2);  // overwrite (kt-1)%3; issue overlaps MMAs

        const uint32_t st = sb + (uint32_t)(kt % STAGES) * STAGEB;
        // mode: 0 main, 1 aug->accG, 2 aug->accU
        int mode = 0;
        if (kt >= NKM) mode = (DUAL && kt >= NKM+2) ? 2 : 1;

        #pragma unroll
        for (int ks = 0; ks < 4; ++ks){
            const int kb = ks*32;
            uint32_t a0[4], a1[4], bb[JN/2][4];
            LDM4(a0, ldaddr(st, wm*32,    kb));
            LDM4(a1, ldaddr(st, wm*32+16, kb));
            #pragma unroll
            for (int g = 0; g < JN/2; ++g)
                LDM4(bb[g], ldaddr(st+PA, wn*WTN + g*16, kb));

            if (mode != 2){
                #pragma unroll
                for (int j = 0; j < JN; ++j){
                    const uint32_t bx = bb[j>>1][j&1], by = bb[j>>1][(j&1)+2];
                    MMA(accG[0][j], a0[0],a0[1],a0[2],a0[3], bx, by);
                    MMA(accG[1][j], a1[0],a1[1],a1[2],a1[3], bx, by);
                }
            } else {
                #pragma unroll
                for (int j = 0; j < JN; ++j){
                    const uint32_t bx = bb[j>>1][j&1], by = bb[j>>1][(j&1)+2];
                    MMA(accU[0][j], a0[0],a0[1],a0[2],a0[3], bx, by);
                    MMA(accU[1][j], a1[0],a1[1],a1[2],a1[3], bx, by);
                }
            }
            if constexpr (DUAL){
                if (mode == 0){
                    #pragma unroll
                    for (int g = 0; g < JN/2; ++g)
                        LDM4(bb[g], ldaddr(st+PA+PB, wn*WTN + g*16, kb));
                    #pragma unroll
                    for (int j = 0; j < JN; ++j){
                        const uint32_t bx = bb[j>>1][j&1], by = bb[j>>1][(j&1)+2];
                        MMA(accU[0][j], a0[0],a0[1],a0[2],a0[3], bx, by);
                        MMA(accU[1][j], a1[0],a1[1],a1[2],a1[3], bx, by);
                    }
                }
            }
        }
    }

    // ---------------- epilogue ----------------
    #pragma unroll
    for (int m = 0; m < 2; ++m){
        #pragma unroll
        for (int j = 0; j < JN; ++j){
            const int r0 = m0 + wm*32 + m*16 + (lane >> 2);
            const int c0 = n0 + wn*WTN + j*8 + (lane & 3)*2;
            if constexpr (DUAL){
                h16* gh = (h16*)g_h_;
                float hv[4];
                #pragma unroll
                for (int q = 0; q < 4; ++q){
                    const float g = accG[m][j][q], u = accU[m][j][q];
                    hv[q] = g * u / (1.f + __expf(-g));
                }
                *(__half2*)(gh + (size_t)r0*MWIDTH + c0)     = __floats2half2_rn(hv[0], hv[1]);
                *(__half2*)(gh + (size_t)(r0+8)*MWIDTH + c0) = __floats2half2_rn(hv[2], hv[3]);
            } else {
                *(float2*)(OutP + (size_t)r0*DMODEL + c0)
                    = make_float2(accG[m][j][0], accG[m][j][1]);
                *(float2*)(OutP + (size_t)(r0+8)*DMODEL + c0)
                    = make_float2(accG[m][j][2], accG[m][j][3]);
            }
        }
    }
}

// ---------------------------------------------------------------------------
extern "C" void kernel_launch(void* const* d_in, const int* in_sizes, int n_in,
                              void* d_out, int out_size)
{
    const float* x  = (const float*)d_in[0];
    const float* Wr = (const float*)d_in[1];
    const float* br = (const float*)d_in[2];
    const float* Wg = (const float*)d_in[3];
    const float* Wu = (const float*)d_in[4];
    const float* Wd = (const float*)d_in[5];
    const float* Ag = (const float*)d_in[6];
    const float* Au = (const float*)d_in[7];
    const float* Ad = (const float*)d_in[8];
    const float* Bg = (const float*)d_in[9];
    const float* Bu = (const float*)d_in[10];
    const float* Bd = (const float*)d_in[11];

    float* out     = (float*)d_out;
    float* routing = out + (size_t)NTOK * DMODEL;
    float* choice  = routing + NTOK * NEXP;

    void *xp,*wg,*wu,*wd,*bg,*bu,*bd;
    cudaGetSymbolAddress(&xp, g_x_);
    cudaGetSymbolAddress(&wg, g_wg_); cudaGetSymbolAddress(&wu, g_wu_);
    cudaGetSymbolAddress(&wd, g_wd_);
    cudaGetSymbolAddress(&bg, g_bg_); cudaGetSymbolAddress(&bu, g_bu_);
    cudaGetSymbolAddress(&bd, g_bd_);

    const int n4x = NTOK*DMODEL/4, n4w = MWIDTH*DMODEL/4;
    k_half<<<(n4x+255)/256, 256>>>(x, (h16*)xp, n4x);
    k_half3<<<dim3((n4w+255)/256, 3), 256>>>(Wg, (h16*)wg, Wu, (h16*)wu, Wd, (h16*)wd, n4w);
    k_splitB2<<<dim3(MWIDTH, 2), 128>>>(Bg, (h16*)bg, Bu, (h16*)bu, MWIDTH);
    k_splitB<<<DMODEL, 128>>>(Bd, (h16*)bd, DMODEL);

    k_router<<<NTOK, 256>>>(x, Wr, br, Ag, Au, routing, choice);

    const int smem_sz = 3 * 32768;   // 98304 both variants
    cudaFuncSetAttribute(k_mma<true>,  cudaFuncAttributeMaxDynamicSharedMemorySize, smem_sz);
    cudaFuncSetAttribute(k_mma<false>, cudaFuncAttributeMaxDynamicSharedMemorySize, smem_sz);

    k_mma<true><<<dim3(MWIDTH/64, NTOK/128), 256, smem_sz>>>(nullptr);
    k_hd<<<NTOK, 256>>>(Ad, routing);
    k_mma<false><<<dim3(DMODEL/128, NTOK/128), 256, smem_sz>>>(out);
}